// round 8
// baseline (speedup 1.0000x reference)
#include <cuda_runtime.h>
#include <cuda_fp16.h>
#include <math.h>
#include <stdint.h>

#define BB   64
#define LL   512
#define EE   256
#define PR   128          // pos feature width (2*P)
#define KK   512
#define TT   53
#define SR   516          // padded rows (2-halo)
#define NCH  26           // K-chunks of 64 per l0 tile (20 embed + 6 pos)
#define NGI  (4 * NCH)    // flattened chunk count (4 l0 tiles)
#define NST  6            // stage slots
#define STAGE_B 32768     // A(16KB) + B(16KB) per chunk slot
#define SMEM_CONV (NST * STAGE_B + 2048)
#define SMEM_CORR (2 * 64 * 256 * 4)   // 128KB

// ---------------- static device scratch ----------------
__device__ __align__(16) __half g_Eh[BB * SR * EE];    // [b][l+2][e] fp16
__device__ __align__(16) __half g_Ph[BB * SR * PR];    // [b][l+1][p] fp16
__device__ __align__(16) __half g_Wh[5 * KK * EE];     // [d][k][e] fp16
__device__ __align__(16) __half g_Wph[3 * KK * PR];    // [t][k][p] fp16
__device__ __align__(16) float  g_C0w[KK * EE];        // [k][e] fp32
__device__ __align__(16) float  g_CLw[KK * EE];        // [k][e] fp32
__device__ __align__(16) float  g_corr0[BB * KK];
__device__ __align__(16) float  g_corrL[BB * KK];
__device__ __align__(16) float  g_pooled[BB * KK];
__device__ __align__(16) float  g_com[BB * 2048];      // subj(768) obj(768) sent_h(512)

// ---------------- helpers ----------------
__device__ __forceinline__ uint32_t smem_u32(const void* p) {
    uint32_t a;
    asm("{ .reg .u64 t; cvta.to.shared.u64 t, %1; cvt.u32.u64 %0, t; }" : "=r"(a) : "l"(p));
    return a;
}
#define SWZ(off) ((off) ^ (((off) >> 3) & 0x70))
__device__ __forceinline__ void cpa16(uint32_t dst, const void* src) {
    asm volatile("cp.async.cg.shared.global [%0], [%1], 16;" :: "r"(dst), "l"(src) : "memory");
}
#define CP_COMMIT() asm volatile("cp.async.commit_group;" ::: "memory")
#define CP_WAIT(n)  asm volatile("cp.async.wait_group %0;" :: "n"(n) : "memory")
__device__ __forceinline__ void ldsm4(uint32_t* r, uint32_t addr) {
    asm volatile("ldmatrix.sync.aligned.m8n8.x4.shared.b16 {%0,%1,%2,%3}, [%4];"
                 : "=r"(r[0]), "=r"(r[1]), "=r"(r[2]), "=r"(r[3]) : "r"(addr));
}
__device__ __forceinline__ void mma16816(float* c, const uint32_t* a, uint32_t b0, uint32_t b1) {
    asm volatile("mma.sync.aligned.m16n8k16.row.col.f32.f16.f16.f32 "
                 "{%0,%1,%2,%3}, {%4,%5,%6,%7}, {%8,%9}, {%0,%1,%2,%3};"
                 : "+f"(c[0]), "+f"(c[1]), "+f"(c[2]), "+f"(c[3])
                 : "r"(a[0]), "r"(a[1]), "r"(a[2]), "r"(a[3]), "r"(b0), "r"(b1));
}

// ---------------- weight prep: one block per k, smem-staged, all coalesced ----------------
__global__ void __launch_bounds__(256) wprep_kernel(const float* __restrict__ conv_w) {
    const int k = blockIdx.x;            // 512 blocks
    const int tid = threadIdx.x;         // 256
    __shared__ float w[2688];
    const float* src = conv_w + (size_t)k * 2688;
    for (int i = tid; i < 2688; i += 256) w[i] = src[i];
    __syncthreads();
    const int e = tid;
#pragma unroll
    for (int d = 0; d < 5; ++d) {
        float s = 0.f;
#pragma unroll
        for (int j = 0; j < 3; ++j) {
            int t = d - j;
            if (t >= 0 && t < 3) s += w[(j * EE + e) * 3 + t];
        }
        g_Wh[((size_t)d * KK + k) * EE + e] = __float2half(s);
    }
    if (tid < PR) {
#pragma unroll
        for (int t = 0; t < 3; ++t)
            g_Wph[((size_t)t * KK + k) * PR + tid] = __float2half(w[(768 + tid) * 3 + t]);
    }
    g_C0w[(size_t)k * EE + e] = w[(2 * EE + e) * 3 + 0];
    g_CLw[(size_t)k * EE + e] = w[e * 3 + 2];
}

// ---------------- gather (fp16, [l][e]) + halo zeroing, vectorized ----------------
__global__ void __launch_bounds__(256) gather_kernel(const int* __restrict__ context,
                              const int* __restrict__ sdis,
                              const int* __restrict__ odis,
                              const float* __restrict__ etab,
                              const float* __restrict__ ptab) {
    const int b = blockIdx.y;
    const int grp = threadIdx.x >> 5, lane = threadIdx.x & 31;
    __half* Eb = g_Eh + (size_t)b * SR * EE;
    __half* Pb = g_Ph + (size_t)b * SR * PR;
#pragma unroll
    for (int li = 0; li < 4; ++li) {
        int l = blockIdx.x * 32 + grp * 4 + li;
        int row = b * LL + l;
        int tok = context[row];
        const float4* es4 = (const float4*)(etab + (size_t)tok * EE);
        uint2* Erow = (uint2*)(Eb + (size_t)(l + 2) * EE);
#pragma unroll
        for (int it = 0; it < 2; ++it) {
            int j = it * 32 + lane;
            float4 f = es4[j];
            __half2 h01 = __floats2half2_rn(f.x, f.y);
            __half2 h23 = __floats2half2_rn(f.z, f.w);
            uint2 u;
            u.x = *(uint32_t*)&h01; u.y = *(uint32_t*)&h23;
            Erow[j] = u;
        }
        int ds = sdis[row], od = odis[row];
        uint2* Prow = (uint2*)(Pb + (size_t)(l + 1) * PR);
        {
            int j = lane;
            float4 f = (j < 16) ? ((const float4*)(ptab + (size_t)ds * 64))[j]
                                : ((const float4*)(ptab + (size_t)od * 64))[j - 16];
            __half2 h01 = __floats2half2_rn(f.x, f.y);
            __half2 h23 = __floats2half2_rn(f.z, f.w);
            uint2 u;
            u.x = *(uint32_t*)&h01; u.y = *(uint32_t*)&h23;
            Prow[j] = u;
        }
    }
    if (blockIdx.x == 0) {
        const int t = threadIdx.x;
        const __half2 z = __floats2half2_rn(0.f, 0.f);
        const int erows[4] = {0, 1, 514, 515};
        const int prows[4] = {0, 513, 514, 515};
#pragma unroll
        for (int i = 0; i < 2; ++i) {
            int idx = t + i * 256;
            ((__half2*)Eb)[(size_t)erows[idx >> 7] * 128 + (idx & 127)] = z;
        }
        ((__half2*)Pb)[(size_t)prows[t >> 6] * 64 + (t & 63)] = z;
    }
}

// ---------------- batched boundary corrections (weights read once) ----------------
__global__ void __launch_bounds__(256) corrb_kernel() {
    extern __shared__ float es[];                 // e0[64*256] | eL[64*256]
    float* e0s = es;
    float* eLs = es + 64 * 256;
    const int tid = threadIdx.x;                  // 256
    for (int idx = tid; idx < 64 * 256; idx += 256) {
        int b = idx >> 8, e = idx & 255;
        e0s[idx] = __half2float(g_Eh[(size_t)b * SR * EE + 2 * EE + e]);
        eLs[idx] = __half2float(g_Eh[(size_t)b * SR * EE + 513 * EE + e]);
    }
    __syncthreads();
    const int w = tid >> 5, lane = tid & 31;
    const int k = blockIdx.x * 8 + w;             // 64 blocks x 8 warps
    float w0[8], wL[8];
#pragma unroll
    for (int q = 0; q < 8; ++q) {
        w0[q] = g_C0w[(size_t)k * EE + lane + q * 32];
        wL[q] = g_CLw[(size_t)k * EE + lane + q * 32];
    }
    for (int b = 0; b < 64; ++b) {
        float s0 = 0.f, sL = 0.f;
#pragma unroll
        for (int q = 0; q < 8; ++q) {
            s0 += e0s[b * 256 + lane + q * 32] * w0[q];
            sL += eLs[b * 256 + lane + q * 32] * wL[q];
        }
#pragma unroll
        for (int o = 16; o; o >>= 1) {
            s0 += __shfl_xor_sync(0xFFFFFFFFu, s0, o);
            sL += __shfl_xor_sync(0xFFFFFFFFu, sL, o);
        }
        if (lane == 0) {
            g_corr0[(size_t)b * KK + k] = s0;
            g_corrL[(size_t)b * KK + k] = sL;
        }
    }
}

// ---------------- entity span features ----------------
__global__ void __launch_bounds__(256) entity_kernel(const int* __restrict__ sidx,
                              const int* __restrict__ oidx) {
    const int b = blockIdx.x, e = threadIdx.x;    // 256
    const __half* Eb = g_Eh + (size_t)b * SR * EE;
    for (int ent = 0; ent < 2; ++ent) {
        const int* ix = ent ? oidx : sidx;
        int s = ix[b * 2 + 0], en = ix[b * 2 + 1];
        int lo = s < 0 ? 0 : s;
        int hi = en > LL - 1 ? LL - 1 : en;
        float sum = 0.f; int cnt = 0;
        for (int l = lo; l <= hi; ++l) {
            sum += __half2float(Eb[(size_t)(l + 2) * EE + e]); ++cnt;
        }
        float mean = sum / (float)cnt;
        int li = s - 1; if (li < 0) li += LL;
        float left = __half2float(Eb[(size_t)(li + 2) * EE + e]);
        float right = 0.f;
        if (en + 1 < LL) {
            int ri = en + 1; if (ri < 0) ri = 0;
            right = __half2float(Eb[(size_t)(ri + 2) * EE + e]);
        }
        float* dst = g_com + (size_t)b * 2048 + ent * 768;
        dst[e] = mean; dst[256 + e] = left; dst[512 + e] = right;
    }
}

// ---------------- fp16 mma conv + fused max-pool (pair-barrier pipeline) ----------------
__device__ __forceinline__ void stage_chunk(int gi, uint32_t sbase,
                                            const __half* Eb, const __half* Pb,
                                            int k0, int tid) {
    int l0 = (gi / NCH) * 128;
    int c  = gi % NCH;
    const __half* as; const __half* bs; int astr, bstr;
    if (c < 20) {
        int d = c >> 2, ec = c & 3;
        as = Eb + (size_t)(l0 + d) * EE + ec * 64;               astr = EE;
        bs = g_Wh + ((size_t)d * KK + k0) * EE + ec * 64;        bstr = EE;
    } else {
        int cc = c - 20, t = cc >> 1, pc = cc & 1;
        as = Pb + (size_t)(l0 + t) * PR + pc * 64;               astr = PR;
        bs = g_Wph + ((size_t)t * KK + k0) * PR + pc * 64;       bstr = PR;
    }
    const uint32_t st = sbase + (uint32_t)(gi % NST) * STAGE_B;
#pragma unroll
    for (int i = 0; i < 2; ++i) {
        int id = tid + i * 512;
        int r = id >> 3, c16 = id & 7;
        uint32_t off = SWZ((uint32_t)(r * 128 + c16 * 16));
        cpa16(st + off,         (const char*)(as + (size_t)r * astr) + c16 * 16);
        cpa16(st + 16384 + off, (const char*)(bs + (size_t)r * bstr) + c16 * 16);
    }
}

__device__ __forceinline__ void compute_chunk(uint32_t sA, float acc[2][4][4],
                                              int rowA, int rowB, int kbl) {
    const uint32_t sB = sA + 16384;
#pragma unroll
    for (int ks = 0; ks < 4; ++ks) {
        uint32_t a[2][4], bfr[2][4];
#pragma unroll
        for (int mt = 0; mt < 2; ++mt)
            ldsm4(a[mt], sA + SWZ((uint32_t)((rowA + mt * 16) * 128 + ks * 32 + kbl)));
#pragma unroll
        for (int bt = 0; bt < 2; ++bt)
            ldsm4(bfr[bt], sB + SWZ((uint32_t)((rowB + bt * 16) * 128 + ks * 32 + kbl)));
#pragma unroll
        for (int mt = 0; mt < 2; ++mt)
#pragma unroll
            for (int bt = 0; bt < 2; ++bt) {
                mma16816(acc[mt][bt * 2 + 0], a[mt], bfr[bt][0], bfr[bt][2]);
                mma16816(acc[mt][bt * 2 + 1], a[mt], bfr[bt][1], bfr[bt][3]);
            }
    }
}

__global__ void __launch_bounds__(512, 1) conv_mma_kernel(const float* __restrict__ conv_b) {
    extern __shared__ char smem[];
    const uint32_t sbase = smem_u32(smem);
    float* red = (float*)(smem + NST * STAGE_B);
    const int tid = threadIdx.x, wid = tid >> 5, lane = tid & 31;
    const int lw = wid >> 2;            // 0..3 : 32 l-rows
    const int kw = wid & 3;             // 0..3 : 32 k-cols
    const int b = blockIdx.y, k0 = blockIdx.x * 128;
    const __half* Eb = g_Eh + (size_t)b * SR * EE;
    const __half* Pb = g_Ph + (size_t)b * SR * PR;

    const int rquad = lane >> 2, rlo = lane & 3;
    const int rowA = lw * 32 + (lane & 7) + ((lane >> 3) & 1) * 8;
    const int rowB = kw * 32 + (lane & 7) + ((lane >> 3) & 1) * 8;
    const int kbl  = (lane >> 4) * 16;

    float acc[2][4][4];
    float colmax[4][2];
#pragma unroll
    for (int nt = 0; nt < 4; ++nt) { colmax[nt][0] = -3.4e38f; colmax[nt][1] = -3.4e38f; }

    stage_chunk(0, sbase, Eb, Pb, k0, tid); CP_COMMIT();
    stage_chunk(1, sbase, Eb, Pb, k0, tid); CP_COMMIT();
    stage_chunk(2, sbase, Eb, Pb, k0, tid); CP_COMMIT();
    stage_chunk(3, sbase, Eb, Pb, k0, tid); CP_COMMIT();

    for (int p = 0; p < NGI; p += 2) {
        if (p + 2 >= NGI) { CP_WAIT(0); } else { CP_WAIT(2); }
        __syncthreads();
        if (p + 4 < NGI) {
            stage_chunk(p + 4, sbase, Eb, Pb, k0, tid); CP_COMMIT();
            stage_chunk(p + 5, sbase, Eb, Pb, k0, tid); CP_COMMIT();
        }
        if (p % NCH == 0) {
#pragma unroll
            for (int mt = 0; mt < 2; ++mt)
#pragma unroll
                for (int nt = 0; nt < 4; ++nt)
#pragma unroll
                    for (int j = 0; j < 4; ++j) acc[mt][nt][j] = 0.f;
        }
        compute_chunk(sbase + (uint32_t)(p % NST) * STAGE_B, acc, rowA, rowB, kbl);
        compute_chunk(sbase + (uint32_t)((p + 1) % NST) * STAGE_B, acc, rowA, rowB, kbl);

        if (p % NCH == NCH - 2) {       // pair (24,25): end of l0 tile
            const int l0 = (p / NCH) * 128;
            if (l0 == 0 && lw == 0 && rquad == 0) {        // global row 0 (acc[0], c0/c1)
#pragma unroll
                for (int nt = 0; nt < 4; ++nt) {
                    int n = k0 + kw * 32 + nt * 8 + rlo * 2;
                    acc[0][nt][0] -= g_corr0[(size_t)b * KK + n];
                    acc[0][nt][1] -= g_corr0[(size_t)b * KK + n + 1];
                }
            }
            if (l0 == 384 && lw == 3 && rquad == 7) {      // global row 511 (acc[1], c2/c3)
#pragma unroll
                for (int nt = 0; nt < 4; ++nt) {
                    int n = k0 + kw * 32 + nt * 8 + rlo * 2;
                    acc[1][nt][2] -= g_corrL[(size_t)b * KK + n];
                    acc[1][nt][3] -= g_corrL[(size_t)b * KK + n + 1];
                }
            }
#pragma unroll
            for (int mt = 0; mt < 2; ++mt)
#pragma unroll
                for (int nt = 0; nt < 4; ++nt) {
                    colmax[nt][0] = fmaxf(colmax[nt][0], fmaxf(acc[mt][nt][0], acc[mt][nt][2]));
                    colmax[nt][1] = fmaxf(colmax[nt][1], fmaxf(acc[mt][nt][1], acc[mt][nt][3]));
                }
        }
    }
    // reduce over 8 row-quads within warp, then across 4 lw groups
#pragma unroll
    for (int nt = 0; nt < 4; ++nt)
#pragma unroll
        for (int j = 0; j < 2; ++j) {
            float v = colmax[nt][j];
            v = fmaxf(v, __shfl_xor_sync(0xFFFFFFFFu, v, 4));
            v = fmaxf(v, __shfl_xor_sync(0xFFFFFFFFu, v, 8));
            v = fmaxf(v, __shfl_xor_sync(0xFFFFFFFFu, v, 16));
            if (rquad == 0)
                red[lw * 128 + kw * 32 + nt * 8 + rlo * 2 + j] = v;
        }
    __syncthreads();
    if (tid < 128) {
        float m = fmaxf(fmaxf(red[tid], red[128 + tid]),
                        fmaxf(red[256 + tid], red[384 + tid]));
        g_pooled[(size_t)b * KK + k0 + tid] = m + conv_b[k0 + tid];
    }
}

// ---------------- lin1: 8 blocks x 8 batches, weights amortized ----------------
__global__ void __launch_bounds__(512) lin1_kernel(const float* __restrict__ w1,
                                                   const float* __restrict__ b1) {
    const int b0 = blockIdx.x * 8, tid = threadIdx.x;   // 512
    const int w = tid >> 5, lane = tid & 31;
    __shared__ float p[8 * 512];
#pragma unroll
    for (int i = 0; i < 8; ++i)
        p[i * 512 + tid] = g_pooled[(size_t)(b0 + i) * KK + tid];
    __syncthreads();
    const float4* p4 = (const float4*)p;                // [i*128 + j]
    for (int r = 0; r < 32; ++r) {
        int h = r * 16 + w;
        const float4* w4 = (const float4*)(w1 + (size_t)h * KK);
        float s[8] = {0.f, 0.f, 0.f, 0.f, 0.f, 0.f, 0.f, 0.f};
#pragma unroll
        for (int q = 0; q < 4; ++q) {
            int j = lane + q * 32;
            float4 f = w4[j];
#pragma unroll
            for (int i = 0; i < 8; ++i) {
                float4 g = p4[i * 128 + j];
                s[i] += f.x * g.x + f.y * g.y + f.z * g.z + f.w * g.w;
            }
        }
#pragma unroll
        for (int i = 0; i < 8; ++i)
#pragma unroll
            for (int o = 16; o; o >>= 1)
                s[i] += __shfl_xor_sync(0xFFFFFFFFu, s[i], o);
        if (lane == 0) {
            float bb = b1[h];
#pragma unroll
            for (int i = 0; i < 8; ++i)
                g_com[(size_t)(b0 + i) * 2048 + 1536 + h] = tanhf(s[i] + bb);
        }
    }
}

// ---------------- scores: 16 blocks x 4 batches ----------------
__global__ void __launch_bounds__(512) scores_kernel(const float* __restrict__ w2,
                                                     const float* __restrict__ b2,
                                                     float* __restrict__ out) {
    const int b0 = blockIdx.x * 4, tid = threadIdx.x;   // 512
    const int w = tid >> 5, lane = tid & 31;
    __shared__ float c[4 * 2048];                       // 32KB
#pragma unroll
    for (int i = 0; i < 4; ++i)
        for (int j = tid; j < 2048; j += 512)
            c[i * 2048 + j] = g_com[(size_t)(b0 + i) * 2048 + j];
    __syncthreads();
    const float4* c4 = (const float4*)c;                // [i*512 + j]
    for (int t = w; t < TT; t += 16) {
        const float4* w4 = (const float4*)(w2 + (size_t)t * 2048);
        float s[4] = {0.f, 0.f, 0.f, 0.f};
#pragma unroll
        for (int q = 0; q < 16; ++q) {
            int j = lane + q * 32;
            float4 f = w4[j];
#pragma unroll
            for (int i = 0; i < 4; ++i) {
                float4 g = c4[i * 512 + j];
                s[i] += f.x * g.x + f.y * g.y + f.z * g.z + f.w * g.w;
            }
        }
#pragma unroll
        for (int i = 0; i < 4; ++i)
#pragma unroll
            for (int o = 16; o; o >>= 1)
                s[i] += __shfl_xor_sync(0xFFFFFFFFu, s[i], o);
        if (lane == 0) {
            float bb = b2[t];
#pragma unroll
            for (int i = 0; i < 4; ++i)
                out[(size_t)(b0 + i) * TT + t] = s[i] + bb;
        }
    }
}

// ---------------- launch ----------------
extern "C" void kernel_launch(void* const* d_in, const int* in_sizes, int n_in,
                              void* d_out, int out_size) {
    const int*   context = (const int*)  d_in[0];
    const int*   sidx    = (const int*)  d_in[1];
    const int*   oidx    = (const int*)  d_in[2];
    const int*   sdis    = (const int*)  d_in[3];
    const int*   odis    = (const int*)  d_in[4];
    const float* etab    = (const float*)d_in[5];
    const float* ptab    = (const float*)d_in[6];
    const float* conv_w  = (const float*)d_in[7];
    const float* conv_b  = (const float*)d_in[8];
    const float* lin1_w  = (const float*)d_in[9];
    const float* lin1_b  = (const float*)d_in[10];
    const float* lin2_w  = (const float*)d_in[11];
    const float* lin2_b  = (const float*)d_in[12];
    float* out = (float*)d_out;

    cudaFuncSetAttribute(conv_mma_kernel,
                         cudaFuncAttributeMaxDynamicSharedMemorySize, SMEM_CONV);
    cudaFuncSetAttribute(corrb_kernel,
                         cudaFuncAttributeMaxDynamicSharedMemorySize, SMEM_CORR);

    wprep_kernel<<<KK, 256>>>(conv_w);
    gather_kernel<<<dim3(16, BB), 256>>>(context, sdis, odis, etab, ptab);
    corrb_kernel<<<64, 256, SMEM_CORR>>>();
    entity_kernel<<<BB, 256>>>(sidx, oidx);
    conv_mma_kernel<<<dim3(4, BB), 512, SMEM_CONV>>>(conv_b);
    lin1_kernel<<<8, 512>>>(lin1_w, lin1_b);
    scores_kernel<<<16, 512>>>(lin2_w, lin2_b, out);
}

// round 9
// speedup vs baseline: 1.2679x; 1.2679x over previous
#include <cuda_runtime.h>
#include <cuda_fp16.h>
#include <math.h>
#include <stdint.h>

#define BB   64
#define LL   512
#define EE   256
#define PR   128          // pos feature width (2*P)
#define KK   512
#define TT   53
#define SR   516          // padded rows (2-halo)
#define NCH  26           // K-chunks of 64 per l0 tile (20 embed + 6 pos)
#define NGI  (4 * NCH)    // flattened chunk count (4 l0 tiles)
#define NST  3            // stage slots
#define STAGE_B 32768     // A(16KB) + B(16KB) per chunk slot
#define SMEM_CONV (NST * STAGE_B + 1024)
#define SMEM_CORR (2 * 64 * 256 * 4)   // 128KB

// ---------------- static device scratch ----------------
__device__ __align__(16) __half g_Eh[BB * SR * EE];    // [b][l+2][e] fp16
__device__ __align__(16) __half g_Ph[BB * SR * PR];    // [b][l+1][p] fp16
__device__ __align__(16) __half g_Wh[5 * KK * EE];     // [d][k][e] fp16
__device__ __align__(16) __half g_Wph[3 * KK * PR];    // [t][k][p] fp16
__device__ __align__(16) float  g_C0w[KK * EE];        // [k][e] fp32
__device__ __align__(16) float  g_CLw[KK * EE];        // [k][e] fp32
__device__ __align__(16) float  g_corr0[BB * KK];
__device__ __align__(16) float  g_corrL[BB * KK];
__device__ __align__(16) float  g_pooled[BB * KK];
__device__ __align__(16) float  g_com[BB * 2048];      // subj(768) obj(768) sent_h(512)

// ---------------- helpers ----------------
__device__ __forceinline__ uint32_t smem_u32(const void* p) {
    uint32_t a;
    asm("{ .reg .u64 t; cvta.to.shared.u64 t, %1; cvt.u32.u64 %0, t; }" : "=r"(a) : "l"(p));
    return a;
}
#define SWZ(off) ((off) ^ (((off) >> 3) & 0x70))
__device__ __forceinline__ void cpa16(uint32_t dst, const void* src) {
    asm volatile("cp.async.cg.shared.global [%0], [%1], 16;" :: "r"(dst), "l"(src) : "memory");
}
#define CP_COMMIT() asm volatile("cp.async.commit_group;" ::: "memory")
#define CP_WAIT(n)  asm volatile("cp.async.wait_group %0;" :: "n"(n) : "memory")
__device__ __forceinline__ void ldsm4(uint32_t* r, uint32_t addr) {
    asm volatile("ldmatrix.sync.aligned.m8n8.x4.shared.b16 {%0,%1,%2,%3}, [%4];"
                 : "=r"(r[0]), "=r"(r[1]), "=r"(r[2]), "=r"(r[3]) : "r"(addr));
}
__device__ __forceinline__ void mma16816(float* c, const uint32_t* a, uint32_t b0, uint32_t b1) {
    asm volatile("mma.sync.aligned.m16n8k16.row.col.f32.f16.f16.f32 "
                 "{%0,%1,%2,%3}, {%4,%5,%6,%7}, {%8,%9}, {%0,%1,%2,%3};"
                 : "+f"(c[0]), "+f"(c[1]), "+f"(c[2]), "+f"(c[3])
                 : "r"(a[0]), "r"(a[1]), "r"(a[2]), "r"(a[3]), "r"(b0), "r"(b1));
}

// ---------------- weight prep: one block per k, smem-staged, all coalesced ----------------
__global__ void __launch_bounds__(256) wprep_kernel(const float* __restrict__ conv_w) {
    const int k = blockIdx.x;            // 512 blocks
    const int tid = threadIdx.x;         // 256
    __shared__ float w[2688];
    const float* src = conv_w + (size_t)k * 2688;
    for (int i = tid; i < 2688; i += 256) w[i] = src[i];
    __syncthreads();
    const int e = tid;
#pragma unroll
    for (int d = 0; d < 5; ++d) {
        float s = 0.f;
#pragma unroll
        for (int j = 0; j < 3; ++j) {
            int t = d - j;
            if (t >= 0 && t < 3) s += w[(j * EE + e) * 3 + t];
        }
        g_Wh[((size_t)d * KK + k) * EE + e] = __float2half(s);
    }
    if (tid < PR) {
#pragma unroll
        for (int t = 0; t < 3; ++t)
            g_Wph[((size_t)t * KK + k) * PR + tid] = __float2half(w[(768 + tid) * 3 + t]);
    }
    g_C0w[(size_t)k * EE + e] = w[(2 * EE + e) * 3 + 0];
    g_CLw[(size_t)k * EE + e] = w[e * 3 + 2];
}

// ---------------- gather (fp16, [l][e]) + halo zeroing, vectorized ----------------
__global__ void __launch_bounds__(256) gather_kernel(const int* __restrict__ context,
                              const int* __restrict__ sdis,
                              const int* __restrict__ odis,
                              const float* __restrict__ etab,
                              const float* __restrict__ ptab) {
    const int b = blockIdx.y;
    const int grp = threadIdx.x >> 5, lane = threadIdx.x & 31;
    __half* Eb = g_Eh + (size_t)b * SR * EE;
    __half* Pb = g_Ph + (size_t)b * SR * PR;
#pragma unroll
    for (int li = 0; li < 4; ++li) {
        int l = blockIdx.x * 32 + grp * 4 + li;
        int row = b * LL + l;
        int tok = context[row];
        const float4* es4 = (const float4*)(etab + (size_t)tok * EE);
        uint2* Erow = (uint2*)(Eb + (size_t)(l + 2) * EE);
#pragma unroll
        for (int it = 0; it < 2; ++it) {
            int j = it * 32 + lane;
            float4 f = es4[j];
            __half2 h01 = __floats2half2_rn(f.x, f.y);
            __half2 h23 = __floats2half2_rn(f.z, f.w);
            uint2 u;
            u.x = *(uint32_t*)&h01; u.y = *(uint32_t*)&h23;
            Erow[j] = u;
        }
        int ds = sdis[row], od = odis[row];
        uint2* Prow = (uint2*)(Pb + (size_t)(l + 1) * PR);
        {
            int j = lane;
            float4 f = (j < 16) ? ((const float4*)(ptab + (size_t)ds * 64))[j]
                                : ((const float4*)(ptab + (size_t)od * 64))[j - 16];
            __half2 h01 = __floats2half2_rn(f.x, f.y);
            __half2 h23 = __floats2half2_rn(f.z, f.w);
            uint2 u;
            u.x = *(uint32_t*)&h01; u.y = *(uint32_t*)&h23;
            Prow[j] = u;
        }
    }
    if (blockIdx.x == 0) {
        const int t = threadIdx.x;
        const __half2 z = __floats2half2_rn(0.f, 0.f);
        const int erows[4] = {0, 1, 514, 515};
        const int prows[4] = {0, 513, 514, 515};
#pragma unroll
        for (int i = 0; i < 2; ++i) {
            int idx = t + i * 256;
            ((__half2*)Eb)[(size_t)erows[idx >> 7] * 128 + (idx & 127)] = z;
        }
        ((__half2*)Pb)[(size_t)prows[t >> 6] * 64 + (t & 63)] = z;
    }
}

// ---------------- batched boundary corrections (weights read once) ----------------
__global__ void __launch_bounds__(256) corrb_kernel() {
    extern __shared__ float es[];                 // e0[64*256] | eL[64*256]
    float* e0s = es;
    float* eLs = es + 64 * 256;
    const int tid = threadIdx.x;                  // 256
    for (int idx = tid; idx < 64 * 256; idx += 256) {
        int b = idx >> 8, e = idx & 255;
        e0s[idx] = __half2float(g_Eh[(size_t)b * SR * EE + 2 * EE + e]);
        eLs[idx] = __half2float(g_Eh[(size_t)b * SR * EE + 513 * EE + e]);
    }
    __syncthreads();
    const int w = tid >> 5, lane = tid & 31;
    const int k = blockIdx.x * 8 + w;             // 64 blocks x 8 warps
    float w0[8], wL[8];
#pragma unroll
    for (int q = 0; q < 8; ++q) {
        w0[q] = g_C0w[(size_t)k * EE + lane + q * 32];
        wL[q] = g_CLw[(size_t)k * EE + lane + q * 32];
    }
    for (int b = 0; b < 64; ++b) {
        float s0 = 0.f, sL = 0.f;
#pragma unroll
        for (int q = 0; q < 8; ++q) {
            s0 += e0s[b * 256 + lane + q * 32] * w0[q];
            sL += eLs[b * 256 + lane + q * 32] * wL[q];
        }
#pragma unroll
        for (int o = 16; o; o >>= 1) {
            s0 += __shfl_xor_sync(0xFFFFFFFFu, s0, o);
            sL += __shfl_xor_sync(0xFFFFFFFFu, sL, o);
        }
        if (lane == 0) {
            g_corr0[(size_t)b * KK + k] = s0;
            g_corrL[(size_t)b * KK + k] = sL;
        }
    }
}

// ---------------- entity span features ----------------
__global__ void __launch_bounds__(256) entity_kernel(const int* __restrict__ sidx,
                              const int* __restrict__ oidx) {
    const int b = blockIdx.x, e = threadIdx.x;    // 256
    const __half* Eb = g_Eh + (size_t)b * SR * EE;
    for (int ent = 0; ent < 2; ++ent) {
        const int* ix = ent ? oidx : sidx;
        int s = ix[b * 2 + 0], en = ix[b * 2 + 1];
        int lo = s < 0 ? 0 : s;
        int hi = en > LL - 1 ? LL - 1 : en;
        float sum = 0.f; int cnt = 0;
        for (int l = lo; l <= hi; ++l) {
            sum += __half2float(Eb[(size_t)(l + 2) * EE + e]); ++cnt;
        }
        float mean = sum / (float)cnt;
        int li = s - 1; if (li < 0) li += LL;
        float left = __half2float(Eb[(size_t)(li + 2) * EE + e]);
        float right = 0.f;
        if (en + 1 < LL) {
            int ri = en + 1; if (ri < 0) ri = 0;
            right = __half2float(Eb[(size_t)(ri + 2) * EE + e]);
        }
        float* dst = g_com + (size_t)b * 2048 + ent * 768;
        dst[e] = mean; dst[256 + e] = left; dst[512 + e] = right;
    }
}

// ---------------- fp16 mma conv + fused max-pool (round-6 proven config) ----------------
__device__ __forceinline__ void stage_chunk(int gi, uint32_t sbase,
                                            const __half* Eb, const __half* Pb,
                                            int k0, int tid) {
    int l0 = (gi / NCH) * 128;
    int c  = gi % NCH;
    const __half* as; const __half* bs; int astr, bstr;
    if (c < 20) {
        int d = c >> 2, ec = c & 3;
        as = Eb + (size_t)(l0 + d) * EE + ec * 64;               astr = EE;
        bs = g_Wh + ((size_t)d * KK + k0) * EE + ec * 64;        bstr = EE;
    } else {
        int cc = c - 20, t = cc >> 1, pc = cc & 1;
        as = Pb + (size_t)(l0 + t) * PR + pc * 64;               astr = PR;
        bs = g_Wph + ((size_t)t * KK + k0) * PR + pc * 64;       bstr = PR;
    }
    const uint32_t st = sbase + (uint32_t)(gi % NST) * STAGE_B;
#pragma unroll
    for (int i = 0; i < 4; ++i) {
        int id = tid + i * 256;
        int r = id >> 3, c16 = id & 7;
        uint32_t off = SWZ((uint32_t)(r * 128 + c16 * 16));
        cpa16(st + off,         (const char*)(as + (size_t)r * astr) + c16 * 16);
        cpa16(st + 16384 + off, (const char*)(bs + (size_t)r * bstr) + c16 * 16);
    }
}

__global__ void __launch_bounds__(256, 2) conv_mma_kernel(const float* __restrict__ conv_b) {
    extern __shared__ char smem[];
    const uint32_t sbase = smem_u32(smem);
    float* red = (float*)(smem + NST * STAGE_B);
    const int tid = threadIdx.x, wid = tid >> 5, lane = tid & 31;
    const int lw = wid >> 2;          // 0..1 : 64 l-rows
    const int kw = wid & 3;           // 0..3 : 32 k-cols
    const int b = blockIdx.y, k0 = blockIdx.x * 128;
    const __half* Eb = g_Eh + (size_t)b * SR * EE;
    const __half* Pb = g_Ph + (size_t)b * SR * PR;

    const int rquad = lane >> 2, rlo = lane & 3;
    const int rowA = lw * 64 + (lane & 7) + ((lane >> 3) & 1) * 8;
    const int rowB = kw * 32 + (lane & 7) + ((lane >> 3) & 1) * 8;
    const int kbl  = (lane >> 4) * 16;

    float acc[4][4][4];
    float colmax[4][2];
#pragma unroll
    for (int nt = 0; nt < 4; ++nt) { colmax[nt][0] = -3.4e38f; colmax[nt][1] = -3.4e38f; }

    stage_chunk(0, sbase, Eb, Pb, k0, tid); CP_COMMIT();
    stage_chunk(1, sbase, Eb, Pb, k0, tid); CP_COMMIT();

    for (int gi = 0; gi < NGI; ++gi) {
        if (gi == NGI - 1) { CP_WAIT(0); } else { CP_WAIT(1); }
        __syncthreads();
        if (gi + 2 < NGI) { stage_chunk(gi + 2, sbase, Eb, Pb, k0, tid); CP_COMMIT(); }
        if (gi % NCH == 0) {
#pragma unroll
            for (int mt = 0; mt < 4; ++mt)
#pragma unroll
                for (int nt = 0; nt < 4; ++nt)
#pragma unroll
                    for (int j = 0; j < 4; ++j) acc[mt][nt][j] = 0.f;
        }
        const uint32_t sA = sbase + (uint32_t)(gi % NST) * STAGE_B;
        const uint32_t sB = sA + 16384;
#pragma unroll
        for (int ks = 0; ks < 4; ++ks) {
            uint32_t a[4][4], bf[2][4];
#pragma unroll
            for (int mt = 0; mt < 4; ++mt)
                ldsm4(a[mt], sA + SWZ((uint32_t)((rowA + mt * 16) * 128 + ks * 32 + kbl)));
#pragma unroll
            for (int bt = 0; bt < 2; ++bt)
                ldsm4(bf[bt], sB + SWZ((uint32_t)((rowB + bt * 16) * 128 + ks * 32 + kbl)));
#pragma unroll
            for (int mt = 0; mt < 4; ++mt) {
                mma16816(acc[mt][0], a[mt], bf[0][0], bf[0][2]);
                mma16816(acc[mt][1], a[mt], bf[0][1], bf[0][3]);
                mma16816(acc[mt][2], a[mt], bf[1][0], bf[1][2]);
                mma16816(acc[mt][3], a[mt], bf[1][1], bf[1][3]);
            }
        }
        if (gi % NCH == NCH - 1) {
            const int l0 = (gi / NCH) * 128;
            if (l0 == 0 && lw == 0 && rquad == 0) {        // global row 0
#pragma unroll
                for (int nt = 0; nt < 4; ++nt) {
                    int n = k0 + kw * 32 + nt * 8 + rlo * 2;
                    acc[0][nt][0] -= g_corr0[(size_t)b * KK + n];
                    acc[0][nt][1] -= g_corr0[(size_t)b * KK + n + 1];
                }
            }
            if (l0 == 384 && lw == 1 && rquad == 7) {      // global row 511
#pragma unroll
                for (int nt = 0; nt < 4; ++nt) {
                    int n = k0 + kw * 32 + nt * 8 + rlo * 2;
                    acc[3][nt][2] -= g_corrL[(size_t)b * KK + n];
                    acc[3][nt][3] -= g_corrL[(size_t)b * KK + n + 1];
                }
            }
#pragma unroll
            for (int mt = 0; mt < 4; ++mt)
#pragma unroll
                for (int nt = 0; nt < 4; ++nt) {
                    colmax[nt][0] = fmaxf(colmax[nt][0], fmaxf(acc[mt][nt][0], acc[mt][nt][2]));
                    colmax[nt][1] = fmaxf(colmax[nt][1], fmaxf(acc[mt][nt][1], acc[mt][nt][3]));
                }
        }
    }
    // reduce over 8 row-quads then across lw groups
#pragma unroll
    for (int nt = 0; nt < 4; ++nt)
#pragma unroll
        for (int j = 0; j < 2; ++j) {
            float v = colmax[nt][j];
            v = fmaxf(v, __shfl_xor_sync(0xFFFFFFFFu, v, 4));
            v = fmaxf(v, __shfl_xor_sync(0xFFFFFFFFu, v, 8));
            v = fmaxf(v, __shfl_xor_sync(0xFFFFFFFFu, v, 16));
            if (rquad == 0)
                red[lw * 128 + kw * 32 + nt * 8 + rlo * 2 + j] = v;
        }
    __syncthreads();
    if (tid < 128)
        g_pooled[(size_t)b * KK + k0 + tid] =
            fmaxf(red[tid], red[128 + tid]) + conv_b[k0 + tid];
}

// ---------------- lin1: 64 blocks, warp-per-h-row, weights in regs ----------------
__global__ void __launch_bounds__(256) lin1_kernel(const float* __restrict__ w1,
                                                   const float* __restrict__ b1) {
    const int tid = threadIdx.x;
    const int w = tid >> 5, lane = tid & 31;
    const int h = blockIdx.x * 8 + w;             // 64 blocks x 8 warps
    const float4* w4 = (const float4*)(w1 + (size_t)h * KK);
    float4 f[4];
#pragma unroll
    for (int q = 0; q < 4; ++q) f[q] = w4[lane + q * 32];
    const float bb = b1[h];
    for (int b = 0; b < BB; ++b) {
        const float4* p4 = (const float4*)(g_pooled + (size_t)b * KK);
        float s = 0.f;
#pragma unroll
        for (int q = 0; q < 4; ++q) {
            float4 g = p4[lane + q * 32];
            s += f[q].x * g.x + f[q].y * g.y + f[q].z * g.z + f[q].w * g.w;
        }
#pragma unroll
        for (int o = 16; o; o >>= 1) s += __shfl_xor_sync(0xFFFFFFFFu, s, o);
        if (lane == 0)
            g_com[(size_t)b * 2048 + 1536 + h] = tanhf(s + bb);
    }
}

// ---------------- scores: 53 blocks (one per class), warp-per-8-batches ----------------
__global__ void __launch_bounds__(256) scores_kernel(const float* __restrict__ w2,
                                                     const float* __restrict__ b2,
                                                     float* __restrict__ out) {
    const int t = blockIdx.x, tid = threadIdx.x;  // TT blocks, 256 threads
    const int w = tid >> 5, lane = tid & 31;
    __shared__ float wrow[2048];
    for (int i = tid; i < 2048; i += 256) wrow[i] = w2[(size_t)t * 2048 + i];
    __syncthreads();
    const float4* w4 = (const float4*)wrow;
    const float bb = b2[t];
#pragma unroll
    for (int bi = 0; bi < 8; ++bi) {
        int b = w * 8 + bi;
        const float4* c4 = (const float4*)(g_com + (size_t)b * 2048);
        float s = 0.f;
#pragma unroll
        for (int q = 0; q < 16; ++q) {
            int j = lane + q * 32;
            float4 f = w4[j], g = c4[j];
            s += f.x * g.x + f.y * g.y + f.z * g.z + f.w * g.w;
        }
#pragma unroll
        for (int o = 16; o; o >>= 1) s += __shfl_xor_sync(0xFFFFFFFFu, s, o);
        if (lane == 0) out[(size_t)b * TT + t] = s + bb;
    }
}

// ---------------- launch ----------------
extern "C" void kernel_launch(void* const* d_in, const int* in_sizes, int n_in,
                              void* d_out, int out_size) {
    const int*   context = (const int*)  d_in[0];
    const int*   sidx    = (const int*)  d_in[1];
    const int*   oidx    = (const int*)  d_in[2];
    const int*   sdis    = (const int*)  d_in[3];
    const int*   odis    = (const int*)  d_in[4];
    const float* etab    = (const float*)d_in[5];
    const float* ptab    = (const float*)d_in[6];
    const float* conv_w  = (const float*)d_in[7];
    const float* conv_b  = (const float*)d_in[8];
    const float* lin1_w  = (const float*)d_in[9];
    const float* lin1_b  = (const float*)d_in[10];
    const float* lin2_w  = (const float*)d_in[11];
    const float* lin2_b  = (const float*)d_in[12];
    float* out = (float*)d_out;

    cudaFuncSetAttribute(conv_mma_kernel,
                         cudaFuncAttributeMaxDynamicSharedMemorySize, SMEM_CONV);
    cudaFuncSetAttribute(corrb_kernel,
                         cudaFuncAttributeMaxDynamicSharedMemorySize, SMEM_CORR);

    wprep_kernel<<<KK, 256>>>(conv_w);
    gather_kernel<<<dim3(16, BB), 256>>>(context, sdis, odis, etab, ptab);
    corrb_kernel<<<64, 256, SMEM_CORR>>>();
    entity_kernel<<<BB, 256>>>(sidx, oidx);
    conv_mma_kernel<<<dim3(4, BB), 256, SMEM_CONV>>>(conv_b);
    lin1_kernel<<<64, 256>>>(lin1_w, lin1_b);
    scores_kernel<<<TT, 256>>>(lin2_w, lin2_b, out);
}

// round 10
// speedup vs baseline: 1.3184x; 1.0399x over previous
#include <cuda_runtime.h>
#include <cuda_fp16.h>
#include <math.h>
#include <stdint.h>

#define BB   64
#define LL   512
#define EE   256
#define PR   128          // pos feature width (2*P)
#define KK   512
#define TT   53
#define SR   516          // padded rows (2-halo)
#define NCH  26           // K-chunks of 64 per l0 tile (20 embed + 6 pos)
#define NGI  (4 * NCH)    // flattened chunk count (4 l0 tiles)
#define NST  3            // stage slots
#define STAGE_B 32768     // A(16KB) + B(16KB) per chunk slot
#define SMEM_CONV (NST * STAGE_B + 1024)
#define SMEM_CORR (2 * 64 * 256 * 4)   // 128KB

// ---------------- static device scratch ----------------
__device__ __align__(16) __half g_Eh[BB * SR * EE];    // [b][l+2][e] fp16
__device__ __align__(16) __half g_Ph[BB * SR * PR];    // [b][l+1][p] fp16
__device__ __align__(16) __half g_Wh[5 * KK * EE];     // [d][k][e] fp16
__device__ __align__(16) __half g_Wph[3 * KK * PR];    // [t][k][p] fp16
__device__ __align__(16) float  g_C0w[KK * EE];        // [k][e] fp32
__device__ __align__(16) float  g_CLw[KK * EE];        // [k][e] fp32
__device__ __align__(16) float  g_corr0[BB * KK];
__device__ __align__(16) float  g_corrL[BB * KK];
__device__ __align__(16) float  g_pooled[BB * KK];
__device__ __align__(16) float  g_com[BB * 2048];      // subj(768) obj(768) sent_h(512)

// ---------------- helpers ----------------
__device__ __forceinline__ uint32_t smem_u32(const void* p) {
    uint32_t a;
    asm("{ .reg .u64 t; cvta.to.shared.u64 t, %1; cvt.u32.u64 %0, t; }" : "=r"(a) : "l"(p));
    return a;
}
#define SWZ(off) ((off) ^ (((off) >> 3) & 0x70))
__device__ __forceinline__ void cpa16(uint32_t dst, const void* src) {
    asm volatile("cp.async.cg.shared.global [%0], [%1], 16;" :: "r"(dst), "l"(src) : "memory");
}
#define CP_COMMIT() asm volatile("cp.async.commit_group;" ::: "memory")
#define CP_WAIT(n)  asm volatile("cp.async.wait_group %0;" :: "n"(n) : "memory")
__device__ __forceinline__ void ldsm4(uint32_t* r, uint32_t addr) {
    asm volatile("ldmatrix.sync.aligned.m8n8.x4.shared.b16 {%0,%1,%2,%3}, [%4];"
                 : "=r"(r[0]), "=r"(r[1]), "=r"(r[2]), "=r"(r[3]) : "r"(addr));
}
__device__ __forceinline__ void mma16816(float* c, const uint32_t* a, uint32_t b0, uint32_t b1) {
    asm volatile("mma.sync.aligned.m16n8k16.row.col.f32.f16.f16.f32 "
                 "{%0,%1,%2,%3}, {%4,%5,%6,%7}, {%8,%9}, {%0,%1,%2,%3};"
                 : "+f"(c[0]), "+f"(c[1]), "+f"(c[2]), "+f"(c[3])
                 : "r"(a[0]), "r"(a[1]), "r"(a[2]), "r"(a[3]), "r"(b0), "r"(b1));
}

// ---------------- fused prep: wprep (blocks 0..511) + gather (blocks 512..1535) ----------------
__global__ void __launch_bounds__(256) prep_kernel(const float* __restrict__ conv_w,
                                                   const int* __restrict__ context,
                                                   const int* __restrict__ sdis,
                                                   const int* __restrict__ odis,
                                                   const float* __restrict__ etab,
                                                   const float* __restrict__ ptab) {
    const int tid = threadIdx.x;
    if (blockIdx.x < 512) {
        // ---- weight prep: one block per k ----
        const int k = blockIdx.x;
        __shared__ float w[2688];
        const float* src = conv_w + (size_t)k * 2688;
        for (int i = tid; i < 2688; i += 256) w[i] = src[i];
        __syncthreads();
        const int e = tid;
#pragma unroll
        for (int d = 0; d < 5; ++d) {
            float s = 0.f;
#pragma unroll
            for (int j = 0; j < 3; ++j) {
                int t = d - j;
                if (t >= 0 && t < 3) s += w[(j * EE + e) * 3 + t];
            }
            g_Wh[((size_t)d * KK + k) * EE + e] = __float2half(s);
        }
        if (tid < PR) {
#pragma unroll
            for (int t = 0; t < 3; ++t)
                g_Wph[((size_t)t * KK + k) * PR + tid] = __float2half(w[(768 + tid) * 3 + t]);
        }
        g_C0w[(size_t)k * EE + e] = w[(2 * EE + e) * 3 + 0];
        g_CLw[(size_t)k * EE + e] = w[e * 3 + 2];
    } else {
        // ---- gather + halo zeroing ----
        const int bx = blockIdx.x - 512;
        const int b = bx >> 4, xt = bx & 15;
        const int grp = tid >> 5, lane = tid & 31;
        __half* Eb = g_Eh + (size_t)b * SR * EE;
        __half* Pb = g_Ph + (size_t)b * SR * PR;
#pragma unroll
        for (int li = 0; li < 4; ++li) {
            int l = xt * 32 + grp * 4 + li;
            int row = b * LL + l;
            int tok = context[row];
            const float4* es4 = (const float4*)(etab + (size_t)tok * EE);
            uint2* Erow = (uint2*)(Eb + (size_t)(l + 2) * EE);
#pragma unroll
            for (int it = 0; it < 2; ++it) {
                int j = it * 32 + lane;
                float4 f = es4[j];
                __half2 h01 = __floats2half2_rn(f.x, f.y);
                __half2 h23 = __floats2half2_rn(f.z, f.w);
                uint2 u;
                u.x = *(uint32_t*)&h01; u.y = *(uint32_t*)&h23;
                Erow[j] = u;
            }
            int ds = sdis[row], od = odis[row];
            uint2* Prow = (uint2*)(Pb + (size_t)(l + 1) * PR);
            {
                int j = lane;
                float4 f = (j < 16) ? ((const float4*)(ptab + (size_t)ds * 64))[j]
                                    : ((const float4*)(ptab + (size_t)od * 64))[j - 16];
                __half2 h01 = __floats2half2_rn(f.x, f.y);
                __half2 h23 = __floats2half2_rn(f.z, f.w);
                uint2 u;
                u.x = *(uint32_t*)&h01; u.y = *(uint32_t*)&h23;
                Prow[j] = u;
            }
        }
        if (xt == 0) {
            const __half2 z = __floats2half2_rn(0.f, 0.f);
            const int erows[4] = {0, 1, 514, 515};
            const int prows[4] = {0, 513, 514, 515};
#pragma unroll
            for (int i = 0; i < 2; ++i) {
                int idx = tid + i * 256;
                ((__half2*)Eb)[(size_t)erows[idx >> 7] * 128 + (idx & 127)] = z;
            }
            ((__half2*)Pb)[(size_t)prows[tid >> 6] * 64 + (tid & 63)] = z;
        }
    }
}

// ---------------- fused pre: entity (block b) + batched corrections (k-group b) ----------------
__global__ void __launch_bounds__(256) pre_kernel(const int* __restrict__ sidx,
                                                  const int* __restrict__ oidx) {
    extern __shared__ float es[];                 // e0[64*256] | eL[64*256]
    float* e0s = es;
    float* eLs = es + 64 * 256;
    const int tid = threadIdx.x;                  // 256
    for (int idx = tid; idx < 64 * 256; idx += 256) {
        int bb = idx >> 8, e = idx & 255;
        e0s[idx] = __half2float(g_Eh[(size_t)bb * SR * EE + 2 * EE + e]);
        eLs[idx] = __half2float(g_Eh[(size_t)bb * SR * EE + 513 * EE + e]);
    }
    // entity features for b = blockIdx.x (independent of smem staging)
    {
        const int b = blockIdx.x, e = tid;
        const __half* Eb = g_Eh + (size_t)b * SR * EE;
        for (int ent = 0; ent < 2; ++ent) {
            const int* ix = ent ? oidx : sidx;
            int s = ix[b * 2 + 0], en = ix[b * 2 + 1];
            int lo = s < 0 ? 0 : s;
            int hi = en > LL - 1 ? LL - 1 : en;
            float sum = 0.f; int cnt = 0;
            for (int l = lo; l <= hi; ++l) {
                sum += __half2float(Eb[(size_t)(l + 2) * EE + e]); ++cnt;
            }
            float mean = sum / (float)cnt;
            int li = s - 1; if (li < 0) li += LL;
            float left = __half2float(Eb[(size_t)(li + 2) * EE + e]);
            float right = 0.f;
            if (en + 1 < LL) {
                int ri = en + 1; if (ri < 0) ri = 0;
                right = __half2float(Eb[(size_t)(ri + 2) * EE + e]);
            }
            float* dst = g_com + (size_t)b * 2048 + ent * 768;
            dst[e] = mean; dst[256 + e] = left; dst[512 + e] = right;
        }
    }
    __syncthreads();
    // corrections: warp per k, weights read once chip-wide
    const int w = tid >> 5, lane = tid & 31;
    const int k = blockIdx.x * 8 + w;
    float w0[8], wL[8];
#pragma unroll
    for (int q = 0; q < 8; ++q) {
        w0[q] = g_C0w[(size_t)k * EE + lane + q * 32];
        wL[q] = g_CLw[(size_t)k * EE + lane + q * 32];
    }
    for (int b = 0; b < 64; ++b) {
        float s0 = 0.f, sL = 0.f;
#pragma unroll
        for (int q = 0; q < 8; ++q) {
            s0 += e0s[b * 256 + lane + q * 32] * w0[q];
            sL += eLs[b * 256 + lane + q * 32] * wL[q];
        }
#pragma unroll
        for (int o = 16; o; o >>= 1) {
            s0 += __shfl_xor_sync(0xFFFFFFFFu, s0, o);
            sL += __shfl_xor_sync(0xFFFFFFFFu, sL, o);
        }
        if (lane == 0) {
            g_corr0[(size_t)b * KK + k] = s0;
            g_corrL[(size_t)b * KK + k] = sL;
        }
    }
}

// ---------------- fp16 mma conv + fused max-pool (4 warps, 64x64 warp tile) ----------------
__device__ __forceinline__ void stage_chunk(int gi, uint32_t sbase,
                                            const __half* Eb, const __half* Pb,
                                            int k0, int tid) {
    int l0 = (gi / NCH) * 128;
    int c  = gi % NCH;
    const __half* as; const __half* bs; int astr, bstr;
    if (c < 20) {
        int d = c >> 2, ec = c & 3;
        as = Eb + (size_t)(l0 + d) * EE + ec * 64;               astr = EE;
        bs = g_Wh + ((size_t)d * KK + k0) * EE + ec * 64;        bstr = EE;
    } else {
        int cc = c - 20, t = cc >> 1, pc = cc & 1;
        as = Pb + (size_t)(l0 + t) * PR + pc * 64;               astr = PR;
        bs = g_Wph + ((size_t)t * KK + k0) * PR + pc * 64;       bstr = PR;
    }
    const uint32_t st = sbase + (uint32_t)(gi % NST) * STAGE_B;
#pragma unroll
    for (int i = 0; i < 8; ++i) {
        int id = tid + i * 128;
        int r = id >> 3, c16 = id & 7;
        uint32_t off = SWZ((uint32_t)(r * 128 + c16 * 16));
        cpa16(st + off,         (const char*)(as + (size_t)r * astr) + c16 * 16);
        cpa16(st + 16384 + off, (const char*)(bs + (size_t)r * bstr) + c16 * 16);
    }
}

__global__ void __launch_bounds__(128, 2) conv_mma_kernel(const float* __restrict__ conv_b) {
    extern __shared__ char smem[];
    const uint32_t sbase = smem_u32(smem);
    float* red = (float*)(smem + NST * STAGE_B);
    const int tid = threadIdx.x, wid = tid >> 5, lane = tid & 31;
    const int lw = wid >> 1;          // 0..1 : 64 l-rows
    const int kw = wid & 1;           // 0..1 : 64 k-cols
    const int b = blockIdx.y, k0 = blockIdx.x * 128;
    const __half* Eb = g_Eh + (size_t)b * SR * EE;
    const __half* Pb = g_Ph + (size_t)b * SR * PR;

    const int rquad = lane >> 2, rlo = lane & 3;
    const int rowA = lw * 64 + (lane & 7) + ((lane >> 3) & 1) * 8;
    const int rowB = kw * 64 + (lane & 7) + ((lane >> 3) & 1) * 8;
    const int kbl  = (lane >> 4) * 16;

    float acc[4][8][4];
    float colmax[8][2];
#pragma unroll
    for (int nt = 0; nt < 8; ++nt) { colmax[nt][0] = -3.4e38f; colmax[nt][1] = -3.4e38f; }

    stage_chunk(0, sbase, Eb, Pb, k0, tid); CP_COMMIT();
    stage_chunk(1, sbase, Eb, Pb, k0, tid); CP_COMMIT();

    for (int gi = 0; gi < NGI; ++gi) {
        if (gi == NGI - 1) { CP_WAIT(0); } else { CP_WAIT(1); }
        __syncthreads();
        if (gi + 2 < NGI) { stage_chunk(gi + 2, sbase, Eb, Pb, k0, tid); CP_COMMIT(); }
        if (gi % NCH == 0) {
#pragma unroll
            for (int mt = 0; mt < 4; ++mt)
#pragma unroll
                for (int nt = 0; nt < 8; ++nt)
#pragma unroll
                    for (int j = 0; j < 4; ++j) acc[mt][nt][j] = 0.f;
        }
        const uint32_t sA = sbase + (uint32_t)(gi % NST) * STAGE_B;
        const uint32_t sB = sA + 16384;
#pragma unroll
        for (int ks = 0; ks < 4; ++ks) {
            uint32_t a[4][4], bf[4][4];
#pragma unroll
            for (int mt = 0; mt < 4; ++mt)
                ldsm4(a[mt], sA + SWZ((uint32_t)((rowA + mt * 16) * 128 + ks * 32 + kbl)));
#pragma unroll
            for (int bt = 0; bt < 4; ++bt)
                ldsm4(bf[bt], sB + SWZ((uint32_t)((rowB + bt * 16) * 128 + ks * 32 + kbl)));
#pragma unroll
            for (int mt = 0; mt < 4; ++mt)
#pragma unroll
                for (int bt = 0; bt < 4; ++bt) {
                    mma16816(acc[mt][bt * 2 + 0], a[mt], bf[bt][0], bf[bt][2]);
                    mma16816(acc[mt][bt * 2 + 1], a[mt], bf[bt][1], bf[bt][3]);
                }
        }
        if (gi % NCH == NCH - 1) {
            const int l0 = (gi / NCH) * 128;
            if (l0 == 0 && lw == 0 && rquad == 0) {        // global row 0
#pragma unroll
                for (int nt = 0; nt < 8; ++nt) {
                    int n = k0 + kw * 64 + nt * 8 + rlo * 2;
                    acc[0][nt][0] -= g_corr0[(size_t)b * KK + n];
                    acc[0][nt][1] -= g_corr0[(size_t)b * KK + n + 1];
                }
            }
            if (l0 == 384 && lw == 1 && rquad == 7) {      // global row 511
#pragma unroll
                for (int nt = 0; nt < 8; ++nt) {
                    int n = k0 + kw * 64 + nt * 8 + rlo * 2;
                    acc[3][nt][2] -= g_corrL[(size_t)b * KK + n];
                    acc[3][nt][3] -= g_corrL[(size_t)b * KK + n + 1];
                }
            }
#pragma unroll
            for (int mt = 0; mt < 4; ++mt)
#pragma unroll
                for (int nt = 0; nt < 8; ++nt) {
                    colmax[nt][0] = fmaxf(colmax[nt][0], fmaxf(acc[mt][nt][0], acc[mt][nt][2]));
                    colmax[nt][1] = fmaxf(colmax[nt][1], fmaxf(acc[mt][nt][1], acc[mt][nt][3]));
                }
        }
    }
    // reduce over 8 row-quads then across 2 lw groups
#pragma unroll
    for (int nt = 0; nt < 8; ++nt)
#pragma unroll
        for (int j = 0; j < 2; ++j) {
            float v = colmax[nt][j];
            v = fmaxf(v, __shfl_xor_sync(0xFFFFFFFFu, v, 4));
            v = fmaxf(v, __shfl_xor_sync(0xFFFFFFFFu, v, 8));
            v = fmaxf(v, __shfl_xor_sync(0xFFFFFFFFu, v, 16));
            if (rquad == 0)
                red[lw * 128 + kw * 64 + nt * 8 + rlo * 2 + j] = v;
        }
    __syncthreads();
    if (tid < 128)
        g_pooled[(size_t)b * KK + k0 + tid] =
            fmaxf(red[tid], red[128 + tid]) + conv_b[k0 + tid];
}

// ---------------- lin1: 64 blocks, warp-per-h-row, weights in regs ----------------
__global__ void __launch_bounds__(256) lin1_kernel(const float* __restrict__ w1,
                                                   const float* __restrict__ b1) {
    const int tid = threadIdx.x;
    const int w = tid >> 5, lane = tid & 31;
    const int h = blockIdx.x * 8 + w;             // 64 blocks x 8 warps
    const float4* w4 = (const float4*)(w1 + (size_t)h * KK);
    float4 f[4];
#pragma unroll
    for (int q = 0; q < 4; ++q) f[q] = w4[lane + q * 32];
    const float bb = b1[h];
    for (int b = 0; b < BB; ++b) {
        const float4* p4 = (const float4*)(g_pooled + (size_t)b * KK);
        float s = 0.f;
#pragma unroll
        for (int q = 0; q < 4; ++q) {
            float4 g = p4[lane + q * 32];
            s += f[q].x * g.x + f[q].y * g.y + f[q].z * g.z + f[q].w * g.w;
        }
#pragma unroll
        for (int o = 16; o; o >>= 1) s += __shfl_xor_sync(0xFFFFFFFFu, s, o);
        if (lane == 0)
            g_com[(size_t)b * 2048 + 1536 + h] = tanhf(s + bb);
    }
}

// ---------------- scores: 53 blocks (one per class), warp-per-8-batches ----------------
__global__ void __launch_bounds__(256) scores_kernel(const float* __restrict__ w2,
                                                     const float* __restrict__ b2,
                                                     float* __restrict__ out) {
    const int t = blockIdx.x, tid = threadIdx.x;  // TT blocks, 256 threads
    const int w = tid >> 5, lane = tid & 31;
    __shared__ float wrow[2048];
    for (int i = tid; i < 2048; i += 256) wrow[i] = w2[(size_t)t * 2048 + i];
    __syncthreads();
    const float4* w4 = (const float4*)wrow;
    const float bb = b2[t];
#pragma unroll
    for (int bi = 0; bi < 8; ++bi) {
        int b = w * 8 + bi;
        const float4* c4 = (const float4*)(g_com + (size_t)b * 2048);
        float s = 0.f;
#pragma unroll
        for (int q = 0; q < 16; ++q) {
            int j = lane + q * 32;
            float4 f = w4[j], g = c4[j];
            s += f.x * g.x + f.y * g.y + f.z * g.z + f.w * g.w;
        }
#pragma unroll
        for (int o = 16; o; o >>= 1) s += __shfl_xor_sync(0xFFFFFFFFu, s, o);
        if (lane == 0) out[(size_t)b * TT + t] = s + bb;
    }
}

// ---------------- launch ----------------
extern "C" void kernel_launch(void* const* d_in, const int* in_sizes, int n_in,
                              void* d_out, int out_size) {
    const int*   context = (const int*)  d_in[0];
    const int*   sidx    = (const int*)  d_in[1];
    const int*   oidx    = (const int*)  d_in[2];
    const int*   sdis    = (const int*)  d_in[3];
    const int*   odis    = (const int*)  d_in[4];
    const float* etab    = (const float*)d_in[5];
    const float* ptab    = (const float*)d_in[6];
    const float* conv_w  = (const float*)d_in[7];
    const float* conv_b  = (const float*)d_in[8];
    const float* lin1_w  = (const float*)d_in[9];
    const float* lin1_b  = (const float*)d_in[10];
    const float* lin2_w  = (const float*)d_in[11];
    const float* lin2_b  = (const float*)d_in[12];
    float* out = (float*)d_out;

    cudaFuncSetAttribute(conv_mma_kernel,
                         cudaFuncAttributeMaxDynamicSharedMemorySize, SMEM_CONV);
    cudaFuncSetAttribute(pre_kernel,
                         cudaFuncAttributeMaxDynamicSharedMemorySize, SMEM_CORR);

    prep_kernel<<<1536, 256>>>(conv_w, context, sdis, odis, etab, ptab);
    pre_kernel<<<64, 256, SMEM_CORR>>>(sidx, oidx);
    conv_mma_kernel<<<dim3(4, BB), 128, SMEM_CONV>>>(conv_b);
    lin1_kernel<<<64, 256>>>(lin1_w, lin1_b);
    scores_kernel<<<TT, 256>>>(lin2_w, lin2_b, out);
}

// round 12
// speedup vs baseline: 1.3804x; 1.0470x over previous
#include <cuda_runtime.h>
#include <cuda_fp16.h>
#include <math.h>
#include <stdint.h>

#define BB   64
#define LL   512
#define EE   256
#define PR   128          // pos feature width (2*P)
#define KK   512
#define TT   53
#define SR   516          // padded rows (2-halo)
#define NCH  26           // K-chunks of 64 per l0 tile (20 embed + 6 pos)
#define NGI  (4 * NCH)    // flattened chunk count (4 l0 tiles)
#define NST  3            // stage slots
#define STAGE_B 32768     // A(16KB) + B(16KB) per chunk slot
#define SMEM_CONV (NST * STAGE_B + 1024)
#define SMEM_CORR (2 * 64 * 256 * 4)   // 128KB

// ---------------- static device scratch ----------------
__device__ __align__(16) __half g_Eh[BB * SR * EE];    // [b][l+2][e] fp16
__device__ __align__(16) __half g_Ph[BB * SR * PR];    // [b][l+1][p] fp16
__device__ __align__(16) __half g_Wh[5 * KK * EE];     // [d][k][e] fp16
__device__ __align__(16) __half g_Wph[3 * KK * PR];    // [t][k][p] fp16
__device__ __align__(16) float  g_C0w[KK * EE];        // [k][e] fp32
__device__ __align__(16) float  g_CLw[KK * EE];        // [k][e] fp32
__device__ __align__(16) float  g_corr0[BB * KK];
__device__ __align__(16) float  g_corrL[BB * KK];
__device__ __align__(16) float  g_pooled[BB * KK];
__device__ __align__(16) float  g_com[BB * 2048];      // subj(768) obj(768) sent_h(512)

// ---------------- helpers ----------------
__device__ __forceinline__ uint32_t smem_u32(const void* p) {
    uint32_t a;
    asm("{ .reg .u64 t; cvta.to.shared.u64 t, %1; cvt.u32.u64 %0, t; }" : "=r"(a) : "l"(p));
    return a;
}
#define SWZ(off) ((off) ^ (((off) >> 3) & 0x70))
__device__ __forceinline__ void cpa16(uint32_t dst, const void* src) {
    asm volatile("cp.async.cg.shared.global [%0], [%1], 16;" :: "r"(dst), "l"(src) : "memory");
}
#define CP_COMMIT() asm volatile("cp.async.commit_group;" ::: "memory")
#define CP_WAIT(n)  asm volatile("cp.async.wait_group %0;" :: "n"(n) : "memory")
__device__ __forceinline__ void ldsm4(uint32_t* r, uint32_t addr) {
    asm volatile("ldmatrix.sync.aligned.m8n8.x4.shared.b16 {%0,%1,%2,%3}, [%4];"
                 : "=r"(r[0]), "=r"(r[1]), "=r"(r[2]), "=r"(r[3]) : "r"(addr));
}
__device__ __forceinline__ void mma16816(float* c, const uint32_t* a, uint32_t b0, uint32_t b1) {
    asm volatile("mma.sync.aligned.m16n8k16.row.col.f32.f16.f16.f32 "
                 "{%0,%1,%2,%3}, {%4,%5,%6,%7}, {%8,%9}, {%0,%1,%2,%3};"
                 : "+f"(c[0]), "+f"(c[1]), "+f"(c[2]), "+f"(c[3])
                 : "r"(a[0]), "r"(a[1]), "r"(a[2]), "r"(a[3]), "r"(b0), "r"(b1));
}

// ---------------- fused prep: wprep (blocks 0..511) + gather (blocks 512..1535) ----------------
__global__ void __launch_bounds__(256) prep_kernel(const float* __restrict__ conv_w,
                                                   const int* __restrict__ context,
                                                   const int* __restrict__ sdis,
                                                   const int* __restrict__ odis,
                                                   const float* __restrict__ etab,
                                                   const float* __restrict__ ptab) {
    const int tid = threadIdx.x;
    if (blockIdx.x < 512) {
        const int k = blockIdx.x;
        __shared__ float w[2688];
        const float* src = conv_w + (size_t)k * 2688;
        for (int i = tid; i < 2688; i += 256) w[i] = src[i];
        __syncthreads();
        const int e = tid;
#pragma unroll
        for (int d = 0; d < 5; ++d) {
            float s = 0.f;
#pragma unroll
            for (int j = 0; j < 3; ++j) {
                int t = d - j;
                if (t >= 0 && t < 3) s += w[(j * EE + e) * 3 + t];
            }
            g_Wh[((size_t)d * KK + k) * EE + e] = __float2half(s);
        }
        if (tid < PR) {
#pragma unroll
            for (int t = 0; t < 3; ++t)
                g_Wph[((size_t)t * KK + k) * PR + tid] = __float2half(w[(768 + tid) * 3 + t]);
        }
        g_C0w[(size_t)k * EE + e] = w[(2 * EE + e) * 3 + 0];
        g_CLw[(size_t)k * EE + e] = w[e * 3 + 2];
    } else {
        const int bx = blockIdx.x - 512;
        const int b = bx >> 4, xt = bx & 15;
        const int grp = tid >> 5, lane = tid & 31;
        __half* Eb = g_Eh + (size_t)b * SR * EE;
        __half* Pb = g_Ph + (size_t)b * SR * PR;
#pragma unroll
        for (int li = 0; li < 4; ++li) {
            int l = xt * 32 + grp * 4 + li;
            int row = b * LL + l;
            int tok = context[row];
            const float4* es4 = (const float4*)(etab + (size_t)tok * EE);
            uint2* Erow = (uint2*)(Eb + (size_t)(l + 2) * EE);
#pragma unroll
            for (int it = 0; it < 2; ++it) {
                int j = it * 32 + lane;
                float4 f = es4[j];
                __half2 h01 = __floats2half2_rn(f.x, f.y);
                __half2 h23 = __floats2half2_rn(f.z, f.w);
                uint2 u;
                u.x = *(uint32_t*)&h01; u.y = *(uint32_t*)&h23;
                Erow[j] = u;
            }
            int ds = sdis[row], od = odis[row];
            uint2* Prow = (uint2*)(Pb + (size_t)(l + 1) * PR);
            {
                int j = lane;
                float4 f = (j < 16) ? ((const float4*)(ptab + (size_t)ds * 64))[j]
                                    : ((const float4*)(ptab + (size_t)od * 64))[j - 16];
                __half2 h01 = __floats2half2_rn(f.x, f.y);
                __half2 h23 = __floats2half2_rn(f.z, f.w);
                uint2 u;
                u.x = *(uint32_t*)&h01; u.y = *(uint32_t*)&h23;
                Prow[j] = u;
            }
        }
        if (xt == 0) {
            const __half2 z = __floats2half2_rn(0.f, 0.f);
            const int erows[4] = {0, 1, 514, 515};
            const int prows[4] = {0, 513, 514, 515};
#pragma unroll
            for (int i = 0; i < 2; ++i) {
                int idx = tid + i * 256;
                ((__half2*)Eb)[(size_t)erows[idx >> 7] * 128 + (idx & 127)] = z;
            }
            ((__half2*)Pb)[(size_t)prows[tid >> 6] * 64 + (tid & 63)] = z;
        }
    }
}

// ---------------- fused pre: entity (block b) + batched corrections (k-group b) ----------------
__global__ void __launch_bounds__(256) pre_kernel(const int* __restrict__ sidx,
                                                  const int* __restrict__ oidx) {
    extern __shared__ float es[];                 // e0[64*256] | eL[64*256]
    float* e0s = es;
    float* eLs = es + 64 * 256;
    const int tid = threadIdx.x;                  // 256
    for (int idx = tid; idx < 64 * 256; idx += 256) {
        int bb = idx >> 8, e = idx & 255;
        e0s[idx] = __half2float(g_Eh[(size_t)bb * SR * EE + 2 * EE + e]);
        eLs[idx] = __half2float(g_Eh[(size_t)bb * SR * EE + 513 * EE + e]);
    }
    {
        const int b = blockIdx.x, e = tid;
        const __half* Eb = g_Eh + (size_t)b * SR * EE;
        for (int ent = 0; ent < 2; ++ent) {
            const int* ix = ent ? oidx : sidx;
            int s = ix[b * 2 + 0], en = ix[b * 2 + 1];
            int lo = s < 0 ? 0 : s;
            int hi = en > LL - 1 ? LL - 1 : en;
            float sum = 0.f; int cnt = 0;
            for (int l = lo; l <= hi; ++l) {
                sum += __half2float(Eb[(size_t)(l + 2) * EE + e]); ++cnt;
            }
            float mean = sum / (float)cnt;
            int li = s - 1; if (li < 0) li += LL;
            float left = __half2float(Eb[(size_t)(li + 2) * EE + e]);
            float right = 0.f;
            if (en + 1 < LL) {
                int ri = en + 1; if (ri < 0) ri = 0;
                right = __half2float(Eb[(size_t)(ri + 2) * EE + e]);
            }
            float* dst = g_com + (size_t)b * 2048 + ent * 768;
            dst[e] = mean; dst[256 + e] = left; dst[512 + e] = right;
        }
    }
    __syncthreads();
    const int w = tid >> 5, lane = tid & 31;
    const int k = blockIdx.x * 8 + w;
    float w0[8], wL[8];
#pragma unroll
    for (int q = 0; q < 8; ++q) {
        w0[q] = g_C0w[(size_t)k * EE + lane + q * 32];
        wL[q] = g_CLw[(size_t)k * EE + lane + q * 32];
    }
    for (int b = 0; b < 64; ++b) {
        float s0 = 0.f, sL = 0.f;
#pragma unroll
        for (int q = 0; q < 8; ++q) {
            s0 += e0s[b * 256 + lane + q * 32] * w0[q];
            sL += eLs[b * 256 + lane + q * 32] * wL[q];
        }
#pragma unroll
        for (int o = 16; o; o >>= 1) {
            s0 += __shfl_xor_sync(0xFFFFFFFFu, s0, o);
            sL += __shfl_xor_sync(0xFFFFFFFFu, sL, o);
        }
        if (lane == 0) {
            g_corr0[(size_t)b * KK + k] = s0;
            g_corrL[(size_t)b * KK + k] = sL;
        }
    }
}

// ---------------- fp16 mma conv + fused max-pool (4 warps, 64x64 warp tile) ----------------
__device__ __forceinline__ void stage_chunk(int gi, uint32_t sbase,
                                            const __half* Eb, const __half* Pb,
                                            int k0, int tid) {
    int l0 = (gi / NCH) * 128;
    int c  = gi % NCH;
    const __half* as; const __half* bs; int astr, bstr;
    if (c < 20) {
        int d = c >> 2, ec = c & 3;
        as = Eb + (size_t)(l0 + d) * EE + ec * 64;               astr = EE;
        bs = g_Wh + ((size_t)d * KK + k0) * EE + ec * 64;        bstr = EE;
    } else {
        int cc = c - 20, t = cc >> 1, pc = cc & 1;
        as = Pb + (size_t)(l0 + t) * PR + pc * 64;               astr = PR;
        bs = g_Wph + ((size_t)t * KK + k0) * PR + pc * 64;       bstr = PR;
    }
    const uint32_t st = sbase + (uint32_t)(gi % NST) * STAGE_B;
#pragma unroll
    for (int i = 0; i < 8; ++i) {
        int id = tid + i * 128;
        int r = id >> 3, c16 = id & 7;
        uint32_t off = SWZ((uint32_t)(r * 128 + c16 * 16));
        cpa16(st + off,         (const char*)(as + (size_t)r * astr) + c16 * 16);
        cpa16(st + 16384 + off, (const char*)(bs + (size_t)r * bstr) + c16 * 16);
    }
}

__global__ void __launch_bounds__(128, 2) conv_mma_kernel(const float* __restrict__ conv_b) {
    extern __shared__ char smem[];
    const uint32_t sbase = smem_u32(smem);
    float* red = (float*)(smem + NST * STAGE_B);
    const int tid = threadIdx.x, wid = tid >> 5, lane = tid & 31;
    const int lw = wid >> 1;          // 0..1 : 64 l-rows
    const int kw = wid & 1;           // 0..1 : 64 k-cols
    const int b = blockIdx.y, k0 = blockIdx.x * 128;
    const __half* Eb = g_Eh + (size_t)b * SR * EE;
    const __half* Pb = g_Ph + (size_t)b * SR * PR;

    const int rquad = lane >> 2, rlo = lane & 3;
    const int rowA = lw * 64 + (lane & 7) + ((lane >> 3) & 1) * 8;
    const int rowB = kw * 64 + (lane & 7) + ((lane >> 3) & 1) * 8;
    const int kbl  = (lane >> 4) * 16;

    float acc[4][8][4];
    float colmax[8][2];
#pragma unroll
    for (int nt = 0; nt < 8; ++nt) { colmax[nt][0] = -3.4e38f; colmax[nt][1] = -3.4e38f; }

    stage_chunk(0, sbase, Eb, Pb, k0, tid); CP_COMMIT();
    stage_chunk(1, sbase, Eb, Pb, k0, tid); CP_COMMIT();

    for (int gi = 0; gi < NGI; ++gi) {
        if (gi == NGI - 1) { CP_WAIT(0); } else { CP_WAIT(1); }
        __syncthreads();
        if (gi + 2 < NGI) { stage_chunk(gi + 2, sbase, Eb, Pb, k0, tid); CP_COMMIT(); }
        if (gi % NCH == 0) {
#pragma unroll
            for (int mt = 0; mt < 4; ++mt)
#pragma unroll
                for (int nt = 0; nt < 8; ++nt)
#pragma unroll
                    for (int j = 0; j < 4; ++j) acc[mt][nt][j] = 0.f;
        }
        const uint32_t sA = sbase + (uint32_t)(gi % NST) * STAGE_B;
        const uint32_t sB = sA + 16384;
#pragma unroll
        for (int ks = 0; ks < 4; ++ks) {
            uint32_t a[4][4], bf[4][4];
#pragma unroll
            for (int mt = 0; mt < 4; ++mt)
                ldsm4(a[mt], sA + SWZ((uint32_t)((rowA + mt * 16) * 128 + ks * 32 + kbl)));
#pragma unroll
            for (int bt = 0; bt < 4; ++bt)
                ldsm4(bf[bt], sB + SWZ((uint32_t)((rowB + bt * 16) * 128 + ks * 32 + kbl)));
#pragma unroll
            for (int mt = 0; mt < 4; ++mt)
#pragma unroll
                for (int bt = 0; bt < 4; ++bt) {
                    mma16816(acc[mt][bt * 2 + 0], a[mt], bf[bt][0], bf[bt][2]);
                    mma16816(acc[mt][bt * 2 + 1], a[mt], bf[bt][1], bf[bt][3]);
                }
        }
        if (gi % NCH == NCH - 1) {
            const int l0 = (gi / NCH) * 128;
            if (l0 == 0 && lw == 0 && rquad == 0) {        // global row 0
#pragma unroll
                for (int nt = 0; nt < 8; ++nt) {
                    int n = k0 + kw * 64 + nt * 8 + rlo * 2;
                    acc[0][nt][0] -= g_corr0[(size_t)b * KK + n];
                    acc[0][nt][1] -= g_corr0[(size_t)b * KK + n + 1];
                }
            }
            if (l0 == 384 && lw == 1 && rquad == 7) {      // global row 511
#pragma unroll
                for (int nt = 0; nt < 8; ++nt) {
                    int n = k0 + kw * 64 + nt * 8 + rlo * 2;
                    acc[3][nt][2] -= g_corrL[(size_t)b * KK + n];
                    acc[3][nt][3] -= g_corrL[(size_t)b * KK + n + 1];
                }
            }
#pragma unroll
            for (int mt = 0; mt < 4; ++mt)
#pragma unroll
                for (int nt = 0; nt < 8; ++nt) {
                    colmax[nt][0] = fmaxf(colmax[nt][0], fmaxf(acc[mt][nt][0], acc[mt][nt][2]));
                    colmax[nt][1] = fmaxf(colmax[nt][1], fmaxf(acc[mt][nt][1], acc[mt][nt][3]));
                }
        }
    }
#pragma unroll
    for (int nt = 0; nt < 8; ++nt)
#pragma unroll
        for (int j = 0; j < 2; ++j) {
            float v = colmax[nt][j];
            v = fmaxf(v, __shfl_xor_sync(0xFFFFFFFFu, v, 4));
            v = fmaxf(v, __shfl_xor_sync(0xFFFFFFFFu, v, 8));
            v = fmaxf(v, __shfl_xor_sync(0xFFFFFFFFu, v, 16));
            if (rquad == 0)
                red[lw * 128 + kw * 64 + nt * 8 + rlo * 2 + j] = v;
        }
    __syncthreads();
    if (tid < 128)
        g_pooled[(size_t)b * KK + k0 + tid] =
            fmaxf(red[tid], red[128 + tid]) + conv_b[k0 + tid];
}

// ---------------- lin1 v2: 64x4 grid, smem pooled tile, 16 ILP accumulators ----------------
__global__ void __launch_bounds__(256) lin1_kernel(const float* __restrict__ w1,
                                                   const float* __restrict__ b1) {
    const int tid = threadIdx.x;
    const int w = tid >> 5, lane = tid & 31;
    const int h = blockIdx.x * 8 + w;             // 64 h-groups x 8 warps
    const int b0 = blockIdx.y * 16;               // 4 b-groups x 16 batches
    __shared__ float pt[16 * 512];                // 32KB
#pragma unroll
    for (int i = 0; i < 32; ++i) {
        int idx = tid + i * 256;                  // 8192 floats
        pt[idx] = g_pooled[(size_t)(b0 + (idx >> 9)) * KK + (idx & 511)];
    }
    const float4* w4 = (const float4*)(w1 + (size_t)h * KK);
    float4 f[4];
#pragma unroll
    for (int q = 0; q < 4; ++q) f[q] = w4[lane + q * 32];
    __syncthreads();
    const float4* p4 = (const float4*)pt;         // [i*128 + j]
    float s[16];
#pragma unroll
    for (int i = 0; i < 16; ++i) s[i] = 0.f;
#pragma unroll
    for (int q = 0; q < 4; ++q) {
        int j = lane + q * 32;
#pragma unroll
        for (int i = 0; i < 16; ++i) {
            float4 g = p4[i * 128 + j];
            s[i] += f[q].x * g.x + f[q].y * g.y + f[q].z * g.z + f[q].w * g.w;
        }
    }
#pragma unroll
    for (int o = 16; o; o >>= 1)
#pragma unroll
        for (int i = 0; i < 16; ++i)
            s[i] += __shfl_xor_sync(0xFFFFFFFFu, s[i], o);
    if (lane == 0) {
        const float bb = b1[h];
#pragma unroll
        for (int i = 0; i < 16; ++i)
            g_com[(size_t)(b0 + i) * 2048 + 1536 + h] = tanhf(s[i] + bb);
    }
}

// ---------------- scores v2: 53 blocks, 8 ILP accumulators per warp ----------------
__global__ void __launch_bounds__(256) scores_kernel(const float* __restrict__ w2,
                                                     const float* __restrict__ b2,
                                                     float* __restrict__ out) {
    const int t = blockIdx.x, tid = threadIdx.x;  // TT blocks, 256 threads
    const int w = tid >> 5, lane = tid & 31;
    __shared__ float wrow[2048];
    for (int i = tid; i < 2048; i += 256) wrow[i] = w2[(size_t)t * 2048 + i];
    __syncthreads();
    const float4* w4 = (const float4*)wrow;
    float s[8];
#pragma unroll
    for (int i = 0; i < 8; ++i) s[i] = 0.f;
#pragma unroll
    for (int q = 0; q < 16; ++q) {
        int j = lane + q * 32;
        float4 f = w4[j];
#pragma unroll
        for (int bi = 0; bi < 8; ++bi) {
            const float4* c4 = (const float4*)(g_com + (size_t)(w * 8 + bi) * 2048);
            float4 g = c4[j];
            s[bi] += f.x * g.x + f.y * g.y + f.z * g.z + f.w * g.w;
        }
    }
#pragma unroll
    for (int o = 16; o; o >>= 1)
#pragma unroll
        for (int bi = 0; bi < 8; ++bi)
            s[bi] += __shfl_xor_sync(0xFFFFFFFFu, s[bi], o);
    if (lane == 0) {
        const float bb = b2[t];
#pragma unroll
        for (int bi = 0; bi < 8; ++bi)
            out[(size_t)(w * 8 + bi) * TT + t] = s[bi] + bb;
    }
}

// ---------------- launch ----------------
extern "C" void kernel_launch(void* const* d_in, const int* in_sizes, int n_in,
                              void* d_out, int out_size) {
    const int*   context = (const int*)  d_in[0];
    const int*   sidx    = (const int*)  d_in[1];
    const int*   oidx    = (const int*)  d_in[2];
    const int*   sdis    = (const int*)  d_in[3];
    const int*   odis    = (const int*)  d_in[4];
    const float* etab    = (const float*)d_in[5];
    const float* ptab    = (const float*)d_in[6];
    const float* conv_w  = (const float*)d_in[7];
    const float* conv_b  = (const float*)d_in[8];
    const float* lin1_w  = (const float*)d_in[9];
    const float* lin1_b  = (const float*)d_in[10];
    const float* lin2_w  = (const float*)d_in[11];
    const float* lin2_b  = (const float*)d_in[12];
    float* out = (float*)d_out;

    cudaFuncSetAttribute(conv_mma_kernel,
                         cudaFuncAttributeMaxDynamicSharedMemorySize, SMEM_CONV);
    cudaFuncSetAttribute(pre_kernel,
                         cudaFuncAttributeMaxDynamicSharedMemorySize, SMEM_CORR);

    prep_kernel<<<1536, 256>>>(conv_w, context, sdis, odis, etab, ptab);
    pre_kernel<<<64, 256, SMEM_CORR>>>(sidx, oidx);
    conv_mma_kernel<<<dim3(4, BB), 128, SMEM_CONV>>>(conv_b);
    lin1_kernel<<<dim3(64, 4), 256>>>(lin1_w, lin1_b);
    scores_kernel<<<TT, 256>>>(lin2_w, lin2_b, out);
}